// round 15
// baseline (speedup 1.0000x reference)
#include <cuda_runtime.h>
#include <cuda_bf16.h>
#include <math.h>
#include <stdint.h>

// Problem constants
#define BB 2048
#define SS 24
#define TT 25
#define HH 256
#define EE 300
#define VIN 64
#define VOUT 128
#define G3 768   // 3*H

typedef __nv_bfloat16 bf16;

// ---------------- scratch (device globals; no allocation) ----------------
__device__ float g_encInF[VIN * G3];
__device__ float g_encInB[VIN * G3];
__device__ float g_decEmbW[VOUT * G3];
__device__ float g_decEmbFc[VOUT * VOUT];
__device__ float g_hFa[BB * HH];
__device__ float g_hFb[BB * HH];
__device__ float g_hBa[BB * HH];
__device__ float g_hBb[BB * HH];
__device__ float g_gh1[BB * G3];
__device__ float g_gh2[BB * G3];
__device__ float g_encBse[BB * SS * 2 * HH];   // (B, S, 512) fp32
__device__ float g_encProj[BB * SS * HH];      // (B, S, 256) fp32 (includes attn_b)
__device__ float g_hcat[BB * 2 * HH];
__device__ float g_dhA[BB * HH];
__device__ float g_dhB[BB * HH];
__device__ float g_hWhGh[BB * 1024];           // [hWh(256) | gh(768)] per row
__device__ float g_bcomb[1024];                // [0 | dec_bhh]

// bf16 pair planes (hi / lo), all k-contiguous
__device__ bf16 g_hFaHi[BB * HH]; __device__ bf16 g_hFaLo[BB * HH];
__device__ bf16 g_hFbHi[BB * HH]; __device__ bf16 g_hFbLo[BB * HH];
__device__ bf16 g_hBaHi[BB * HH]; __device__ bf16 g_hBaLo[BB * HH];
__device__ bf16 g_hBbHi[BB * HH]; __device__ bf16 g_hBbLo[BB * HH];
__device__ bf16 g_dhAHi[BB * HH]; __device__ bf16 g_dhALo[BB * HH];
__device__ bf16 g_dhBHi[BB * HH]; __device__ bf16 g_dhBLo[BB * HH];
__device__ bf16 g_WfHi[G3 * HH];  __device__ bf16 g_WfLo[G3 * HH];     // (768,256)
__device__ bf16 g_WbHi[G3 * HH];  __device__ bf16 g_WbLo[G3 * HH];     // (768,256)
__device__ bf16 g_WcombHi[1024 * HH]; __device__ bf16 g_WcombLo[1024 * HH]; // (1024,256)
__device__ bf16 g_Wih2Hi[G3 * 512];   __device__ bf16 g_Wih2Lo[G3 * 512];   // (768,512)
__device__ bf16 g_fcW1Hi[VOUT * G3];  __device__ bf16 g_fcW1Lo[VOUT * G3];  // (128,768)
__device__ bf16 g_catHi[(TT - 1) * BB * G3];
__device__ bf16 g_catLo[(TT - 1) * BB * G3];

__device__ __forceinline__ void split1(float x, bf16& h, bf16& l) {
    h = __float2bfloat16(x);
    l = __float2bfloat16(x - __bfloat162float(h));
}

// ---------------- small kernels ----------------
__global__ void zero_kernel(float* p, int n) {
    int i = blockIdx.x * blockDim.x + threadIdx.x;
    if (i < n) p[i] = 0.0f;
}

__global__ void split_kernel(const float* __restrict__ src,
                             bf16* __restrict__ hi, bf16* __restrict__ lo, int n) {
    int i = blockIdx.x * blockDim.x + threadIdx.x;
    if (i >= n) return;
    bf16 h, l; split1(src[i], h, l);
    hi[i] = h; lo[i] = l;
}

// transpose+split weight: W (K,N) fp32 -> out (N,K) bf16 hi/lo
__global__ void wsplit_kernel(const float* __restrict__ W, int K, int N,
                              bf16* __restrict__ hi, bf16* __restrict__ lo) {
    int t = blockIdx.x * blockDim.x + threadIdx.x;
    if (t >= K * N) return;
    int k = t / N, n = t % N;
    bf16 h, l; split1(W[t], h, l);
    hi[(size_t)n * K + k] = h;
    lo[(size_t)n * K + k] = l;
}

// Wcomb pairs (1024,256) + bcomb
__global__ void comb_split_kernel(const float* __restrict__ attn_Wh,
                                  const float* __restrict__ dec_Whh,
                                  const float* __restrict__ dec_bhh,
                                  bf16* __restrict__ hi, bf16* __restrict__ lo,
                                  float* __restrict__ bias) {
    int t = blockIdx.x * blockDim.x + threadIdx.x;
    if (t >= HH * 1024) return;
    int k = t >> 10, c = t & 1023;
    float v = (c < HH) ? attn_Wh[k * HH + c] : dec_Whh[k * G3 + (c - HH)];
    bf16 h, l; split1(v, h, l);
    hi[(size_t)c * HH + k] = h;
    lo[(size_t)c * HH + k] = l;
    if (k == 0) bias[c] = (c < HH) ? 0.0f : dec_bhh[c - HH];
}

// All 4 embedding-times-weight tables in one launch.
__global__ void tables_kernel(const float* __restrict__ enc_emb,
                              const float* __restrict__ dec_emb,
                              const float* __restrict__ Wf, const float* __restrict__ bf,
                              const float* __restrict__ Wb, const float* __restrict__ bb2,
                              const float* __restrict__ Wd, const float* __restrict__ bd,
                              const float* __restrict__ Wfc, const float* __restrict__ bfc,
                              float* __restrict__ outF, float* __restrict__ outB,
                              float* __restrict__ outD, float* __restrict__ outFc) {
    int t = blockIdx.x * blockDim.x + threadIdx.x;
    const int nF = VIN * G3, nB = VIN * G3, nD = VOUT * G3, nFc = VOUT * VOUT;
    const float* emb; const float* W; const float* bias; float* out; int v, n, N;
    if (t < nF) {
        emb = enc_emb; W = Wf; bias = bf; out = outF; N = G3; v = t / N; n = t % N;
    } else if (t < nF + nB) {
        t -= nF; emb = enc_emb; W = Wb; bias = bb2; out = outB; N = G3; v = t / N; n = t % N;
    } else if (t < nF + nB + nD) {
        t -= nF + nB; emb = dec_emb; W = Wd; bias = bd; out = outD; N = G3; v = t / N; n = t % N;
    } else if (t < nF + nB + nD + nFc) {
        t -= nF + nB + nD; emb = dec_emb; W = Wfc; bias = bfc; out = outFc; N = VOUT; v = t / N; n = t % N;
    } else return;
    float acc = bias[n];
    const float* er = emb + (size_t)v * EE;
    #pragma unroll 4
    for (int e = 0; e < EE; e++) acc += er[e] * W[(size_t)e * N + n];
    out[(size_t)v * N + n] = acc;
}

__global__ void concat2_kernel(const float* __restrict__ a, int na,
                               const float* __restrict__ b2, int nb,
                               float* __restrict__ dst, int rows) {
    int w = na + nb;
    int t = blockIdx.x * blockDim.x + threadIdx.x;
    if (t >= rows * w) return;
    int r = t / w, c = t % w;
    dst[t] = (c < na) ? a[r * na + c] : b2[r * nb + (c - na)];
}

// ==================== shared mma helpers ====================
#define SWZ(o) ((o) ^ (((o) >> 3) & 0x70))

__device__ __forceinline__ uint32_t smem_to_u32(const void* smem_ptr) {
    uint32_t addr;
    asm("{ .reg .u64 tmp; cvta.to.shared.u64 tmp, %1; cvt.u32.u64 %0, tmp; }"
        : "=r"(addr) : "l"(smem_ptr));
    return addr;
}

__device__ __forceinline__ void ldsm_x4(uint32_t* r, uint32_t addr) {
    asm volatile("ldmatrix.sync.aligned.m8n8.x4.shared.b16 {%0,%1,%2,%3}, [%4];"
        : "=r"(r[0]), "=r"(r[1]), "=r"(r[2]), "=r"(r[3]) : "r"(addr));
}

__device__ __forceinline__ void mma_bf16(float* c, const uint32_t* a,
                                         uint32_t b0, uint32_t b1) {
    asm volatile(
        "mma.sync.aligned.m16n8k16.row.col.f32.bf16.bf16.f32 "
        "{%0,%1,%2,%3}, {%4,%5,%6,%7}, {%8,%9}, {%0,%1,%2,%3};"
        : "+f"(c[0]), "+f"(c[1]), "+f"(c[2]), "+f"(c[3])
        : "r"(a[0]), "r"(a[1]), "r"(a[2]), "r"(a[3]), "r"(b0), "r"(b1));
}

__device__ __forceinline__ void split2(float x, float y, uint32_t& hi, uint32_t& lo) {
    bf16 hx = __float2bfloat16(x), hy = __float2bfloat16(y);
    float lxf = x - __bfloat162float(hx);
    float lyf = y - __bfloat162float(hy);
    bf16 lx = __float2bfloat16(lxf), ly = __float2bfloat16(lyf);
    hi = (uint32_t)__bfloat16_as_ushort(hx) | ((uint32_t)__bfloat16_as_ushort(hy) << 16);
    lo = (uint32_t)__bfloat16_as_ushort(lx) | ((uint32_t)__bfloat16_as_ushort(ly) << 16);
}

__device__ __forceinline__ void cpasync16(uint32_t s, const void* g) {
    asm volatile("cp.async.cg.shared.global [%0], [%1], 16;" :: "r"(s), "l"(g));
}
#define CP_COMMIT() asm volatile("cp.async.commit_group;" ::: "memory")
#define CP_WAIT0()  asm volatile("cp.async.wait_group 0;" ::: "memory")

// ==================== pair-operand tensor-core GEMM ====================
#define OFF_AHI  0
#define OFF_ALO  16384
#define OFF_BHI  32768
#define OFF_BLO  40960
#define PSTG     49152
#define PAIR_SMEM (2 * PSTG)

#define STAGE_CHUNK(kcv, stv) do {                                             \
    uint32_t _sbase = sb + (uint32_t)(stv) * PSTG;                             \
    _Pragma("unroll")                                                          \
    for (int _it = 0; _it < 4; _it++) {                                        \
        int _q = tid + _it * 256; int _r = _q >> 3, _j = _q & 7;               \
        size_t _go = (size_t)(row0 + _r) * lda + (kcv) + _j * 8;               \
        uint32_t _so = SWZ((uint32_t)(_r * 128 + _j * 16));                    \
        cpasync16(_sbase + OFF_AHI + _so, AH + _go);                           \
        cpasync16(_sbase + OFF_ALO + _so, AL + _go);                           \
    }                                                                          \
    _Pragma("unroll")                                                          \
    for (int _it = 0; _it < 2; _it++) {                                        \
        int _q = tid + _it * 256; int _r = _q >> 3, _j = _q & 7;               \
        size_t _go = (size_t)(col0 + _r) * ldb + (kcv) + _j * 8;               \
        uint32_t _so = SWZ((uint32_t)(_r * 128 + _j * 16));                    \
        cpasync16(_sbase + OFF_BHI + _so, BH + _go);                           \
        cpasync16(_sbase + OFF_BLO + _so, BL + _go);                           \
    }                                                                          \
    CP_COMMIT();                                                               \
} while (0)

__global__ __launch_bounds__(256) void tc_gemm_pair(
    const bf16* __restrict__ AH0, const bf16* __restrict__ AL0,
    const bf16* __restrict__ AH1, const bf16* __restrict__ AL1, int lda,
    const bf16* __restrict__ BH0, const bf16* __restrict__ BL0,
    const bf16* __restrict__ BH1, const bf16* __restrict__ BL1, int ldb,
    float* __restrict__ C0, float* __restrict__ C1, int ldc, int K,
    const float* __restrict__ bias0, const float* __restrict__ bias1,
    const float* __restrict__ gtab, const int* __restrict__ gidx, int gld) {
    extern __shared__ char smem[];
    uint32_t sb = smem_to_u32(smem);
    const bf16* AH = blockIdx.z ? AH1 : AH0;
    const bf16* AL = blockIdx.z ? AL1 : AL0;
    const bf16* BH = blockIdx.z ? BH1 : BH0;
    const bf16* BL = blockIdx.z ? BL1 : BL0;
    float* C = blockIdx.z ? C1 : C0;
    const float* bias = blockIdx.z ? bias1 : bias0;

    int tid = threadIdx.x;
    int wid = tid >> 5, lane = tid & 31;
    int wr = wid >> 1, wc = wid & 1;
    int row0 = blockIdx.y * 128, col0 = blockIdx.x * 64;

    float acc[2][4][4] = {};

    int a_r  = wr * 32 + (lane & 15);
    int a_kp = (lane >> 4) * 16;
    int b_n  = wc * 32 + ((lane >> 4) << 3) + (lane & 7);
    int b_kp = ((lane >> 3) & 1) * 16;

    int nc = K >> 6;
    STAGE_CHUNK(0, 0);
    CP_WAIT0();
    __syncthreads();

    for (int c = 0; c < nc; c++) {
        int cur = c & 1;
        if (c + 1 < nc) STAGE_CHUNK((c + 1) << 6, cur ^ 1);

        uint32_t sb2 = sb + (uint32_t)cur * PSTG;
        #pragma unroll
        for (int ks = 0; ks < 4; ks++) {
            uint32_t ah[2][4], al[2][4];
            #pragma unroll
            for (int rt = 0; rt < 2; rt++) {
                int r = a_r + rt * 16;
                uint32_t off = (uint32_t)(r * 128) +
                               (uint32_t)((ks * 32 + a_kp) ^ ((r & 7) << 4));
                ldsm_x4(ah[rt], sb2 + OFF_AHI + off);
                ldsm_x4(al[rt], sb2 + OFF_ALO + off);
            }
            uint32_t bh[2][4], bl[2][4];
            #pragma unroll
            for (int cp = 0; cp < 2; cp++) {
                int n = b_n + cp * 16;
                uint32_t off = (uint32_t)(n * 128) +
                               (uint32_t)((ks * 32 + b_kp) ^ ((n & 7) << 4));
                ldsm_x4(bh[cp], sb2 + OFF_BHI + off);
                ldsm_x4(bl[cp], sb2 + OFF_BLO + off);
            }
            #pragma unroll
            for (int rt = 0; rt < 2; rt++)
                #pragma unroll
                for (int ct = 0; ct < 4; ct++) {
                    int cp = ct >> 1, o = (ct & 1) * 2;
                    mma_bf16(acc[rt][ct], ah[rt], bh[cp][o], bh[cp][o + 1]);
                    mma_bf16(acc[rt][ct], ah[rt], bl[cp][o], bl[cp][o + 1]);
                    mma_bf16(acc[rt][ct], al[rt], bh[cp][o], bh[cp][o + 1]);
                }
        }
        if (c + 1 < nc) CP_WAIT0();
        __syncthreads();
    }

    // epilogue
    #pragma unroll
    for (int rt = 0; rt < 2; rt++) {
        int m0 = row0 + wr * 32 + rt * 16 + (lane >> 2);
        int m1 = m0 + 8;
        const float* g0 = gtab ? (gtab + (size_t)gidx[m0] * gld) : nullptr;
        const float* g1 = gtab ? (gtab + (size_t)gidx[m1] * gld) : nullptr;
        #pragma unroll
        for (int ct = 0; ct < 4; ct++) {
            int n = col0 + wc * 32 + ct * 8 + (lane & 3) * 2;
            float v0 = acc[rt][ct][0], v1 = acc[rt][ct][1];
            float v2 = acc[rt][ct][2], v3 = acc[rt][ct][3];
            if (bias) { float b0 = bias[n], b1 = bias[n + 1]; v0 += b0; v1 += b1; v2 += b0; v3 += b1; }
            if (g0) { v0 += g0[n]; v1 += g0[n + 1]; }
            if (g1) { v2 += g1[n]; v3 += g1[n + 1]; }
            *reinterpret_cast<float2*>(&C[(size_t)m0 * ldc + n]) = make_float2(v0, v1);
            *reinterpret_cast<float2*>(&C[(size_t)m1 * ldc + n]) = make_float2(v2, v3);
        }
    }
}

// ==================== fp32-operand tensor-core GEMM ====================
#define F32_SMEM 49152

__global__ __launch_bounds__(256) void tc_gemm_f32(
    const float* __restrict__ A, int lda,
    const float* __restrict__ Bm, int ldb,
    float* __restrict__ C, int ldc,
    int K, const float* __restrict__ bias, int act) {
    extern __shared__ char smem[];
    uint32_t sb = smem_to_u32(smem);

    int tid = threadIdx.x;
    int wid = tid >> 5, lane = tid & 31;
    int wr = wid >> 1, wc = wid & 1;
    int row0 = blockIdx.y * 128, col0 = blockIdx.x * 64;

    float acc[2][4][4] = {};

    int a_r  = wr * 32 + (lane & 15);
    int a_kp = (lane >> 4) * 16;
    int b_n  = wc * 32 + ((lane >> 4) << 3) + (lane & 7);
    int b_kp = ((lane >> 3) & 1) * 16;

    for (int kc = 0; kc < K; kc += 64) {
        #pragma unroll
        for (int it = 0; it < 8; it++) {
            int q = tid + it * 256;
            int r = q >> 4;
            int k4 = (q & 15) * 4;
            float4 v = *reinterpret_cast<const float4*>(
                &A[(size_t)(row0 + r) * lda + kc + k4]);
            uint32_t h01, l01, h23, l23;
            split2(v.x, v.y, h01, l01);
            split2(v.z, v.w, h23, l23);
            uint32_t off = SWZ((uint32_t)(r * 128 + k4 * 2));
            *reinterpret_cast<uint2*>(smem + OFF_AHI + off) = make_uint2(h01, h23);
            *reinterpret_cast<uint2*>(smem + OFF_ALO + off) = make_uint2(l01, l23);
        }
        {
            int n = tid & 63;
            int kh = tid >> 6;
            #pragma unroll
            for (int i = 0; i < 8; i++) {
                int k = kh * 16 + i * 2;
                float b0f = Bm[(size_t)(kc + k) * ldb + col0 + n];
                float b1f = Bm[(size_t)(kc + k + 1) * ldb + col0 + n];
                uint32_t h, l;
                split2(b0f, b1f, h, l);
                uint32_t off = SWZ((uint32_t)(n * 128 + k * 2));
                *reinterpret_cast<uint32_t*>(smem + OFF_BHI + off) = h;
                *reinterpret_cast<uint32_t*>(smem + OFF_BLO + off) = l;
            }
        }
        __syncthreads();

        #pragma unroll
        for (int ks = 0; ks < 4; ks++) {
            uint32_t ah[2][4], al[2][4];
            #pragma unroll
            for (int rt = 0; rt < 2; rt++) {
                int r = a_r + rt * 16;
                uint32_t off = (uint32_t)(r * 128) +
                               (uint32_t)((ks * 32 + a_kp) ^ ((r & 7) << 4));
                ldsm_x4(ah[rt], sb + OFF_AHI + off);
                ldsm_x4(al[rt], sb + OFF_ALO + off);
            }
            uint32_t bh[2][4], bl[2][4];
            #pragma unroll
            for (int cp = 0; cp < 2; cp++) {
                int n = b_n + cp * 16;
                uint32_t off = (uint32_t)(n * 128) +
                               (uint32_t)((ks * 32 + b_kp) ^ ((n & 7) << 4));
                ldsm_x4(bh[cp], sb + OFF_BHI + off);
                ldsm_x4(bl[cp], sb + OFF_BLO + off);
            }
            #pragma unroll
            for (int rt = 0; rt < 2; rt++)
                #pragma unroll
                for (int ct = 0; ct < 4; ct++) {
                    int cp = ct >> 1, o = (ct & 1) * 2;
                    mma_bf16(acc[rt][ct], ah[rt], bh[cp][o], bh[cp][o + 1]);
                    mma_bf16(acc[rt][ct], ah[rt], bl[cp][o], bl[cp][o + 1]);
                    mma_bf16(acc[rt][ct], al[rt], bh[cp][o], bh[cp][o + 1]);
                }
        }
        __syncthreads();
    }

    #pragma unroll
    for (int rt = 0; rt < 2; rt++) {
        int m0 = row0 + wr * 32 + rt * 16 + (lane >> 2);
        int m1 = m0 + 8;
        #pragma unroll
        for (int ct = 0; ct < 4; ct++) {
            int n = col0 + wc * 32 + ct * 8 + (lane & 3) * 2;
            float v0 = acc[rt][ct][0], v1 = acc[rt][ct][1];
            float v2 = acc[rt][ct][2], v3 = acc[rt][ct][3];
            if (bias) { float b0 = bias[n], b1 = bias[n + 1]; v0 += b0; v1 += b1; v2 += b0; v3 += b1; }
            if (act) { v0 = tanhf(v0); v1 = tanhf(v1); v2 = tanhf(v2); v3 = tanhf(v3); }
            *reinterpret_cast<float2*>(&C[(size_t)m0 * ldc + n]) = make_float2(v0, v1);
            *reinterpret_cast<float2*>(&C[(size_t)m1 * ldc + n]) = make_float2(v2, v3);
        }
    }
}

// ---------------- GRU gate kernels ----------------
__global__ void gru_gate_kernel(const float* __restrict__ gi, int gild,
                                const float* __restrict__ gh, int ghld,
                                const float* __restrict__ hprev,
                                float* __restrict__ hout,
                                bf16* __restrict__ houtHi, bf16* __restrict__ houtLo,
                                bf16* __restrict__ catHi, bf16* __restrict__ catLo) {
    int t = blockIdx.x * blockDim.x + threadIdx.x;
    int b = t >> 8;
    int j = t & 255;
    const float* g = gi + (size_t)b * gild;
    const float* G = gh + (size_t)b * ghld;
    float r = 1.0f / (1.0f + __expf(-(g[j] + G[j])));
    float z = 1.0f / (1.0f + __expf(-(g[j + HH] + G[j + HH])));
    float n = tanhf(g[j + 2 * HH] + r * G[j + 2 * HH]);
    float hp = hprev[b * HH + j];
    float hv = (1.0f - z) * n + z * hp;
    hout[b * HH + j] = hv;
    bf16 hh, hl; split1(hv, hh, hl);
    houtHi[b * HH + j] = hh;
    houtLo[b * HH + j] = hl;
    catHi[(size_t)b * G3 + j] = hh;
    catLo[(size_t)b * G3 + j] = hl;
}

__global__ void enc_gate_kernel(const float* __restrict__ giTabF,
                                const float* __restrict__ giTabB,
                                const int* __restrict__ src, int s,
                                const float* __restrict__ ghF,
                                const float* __restrict__ ghB,
                                const float* __restrict__ hprevF,
                                const float* __restrict__ hprevB,
                                float* __restrict__ houtF,
                                float* __restrict__ houtB,
                                bf16* __restrict__ houtFHi, bf16* __restrict__ houtFLo,
                                bf16* __restrict__ houtBHi, bf16* __restrict__ houtBLo,
                                float* __restrict__ encBse) {
    int dir = blockIdx.x >> 11;
    int b = blockIdx.x & (BB - 1);
    int j = threadIdx.x;
    int step = dir ? (SS - 1 - s) : s;
    int tok = src[step * BB + b];
    const float* g = (dir ? giTabB : giTabF) + (size_t)tok * G3;
    const float* G = (dir ? ghB : ghF) + (size_t)b * G3;
    float r = 1.0f / (1.0f + __expf(-(g[j] + G[j])));
    float z = 1.0f / (1.0f + __expf(-(g[j + HH] + G[j + HH])));
    float n = tanhf(g[j + 2 * HH] + r * G[j + 2 * HH]);
    const float* hp = (dir ? hprevB : hprevF) + b * HH;
    float hv = (1.0f - z) * n + z * hp[j];
    (dir ? houtB : houtF)[b * HH + j] = hv;
    bf16 hh, hl; split1(hv, hh, hl);
    (dir ? houtBHi : houtFHi)[b * HH + j] = hh;
    (dir ? houtBLo : houtFLo)[b * HH + j] = hl;
    encBse[((size_t)b * SS + step) * 512 + dir * 256 + j] = hv;
}

// ---------------- fused attention kernel (proj already contains attn_b) ----------------
__global__ __launch_bounds__(256) void attn_kernel(
    const float* __restrict__ hWhGh,   // B x 1024 (first 256 = hWh)
    const float* __restrict__ proj,    // B x S x 256 (with attn_b folded in)
    const float* __restrict__ encBse,  // B x S x 512
    const float* __restrict__ attn_v,  // 256
    bf16* __restrict__ catHi, bf16* __restrict__ catLo) {  // slot base
    int b = blockIdx.x;
    int tid = threadIdx.x;
    __shared__ float hb[256];
    __shared__ float vsh[256];
    __shared__ float sc[SS];
    __shared__ float a_sm[SS];
    hb[tid] = hWhGh[b * 1024 + tid];
    vsh[tid] = attn_v[tid];
    __syncthreads();
    int warp = tid >> 5, lane = tid & 31;
    for (int s = warp; s < SS; s += 8) {
        const float* pr = proj + ((size_t)b * SS + s) * 256;
        float sum = 0.0f;
        #pragma unroll
        for (int i = 0; i < 8; i++) {
            int k = lane + i * 32;
            sum += tanhf(hb[k] + pr[k]) * vsh[k];
        }
        #pragma unroll
        for (int o = 16; o > 0; o >>= 1) sum += __shfl_xor_sync(0xFFFFFFFFu, sum, o);
        if (lane == 0) sc[s] = sum;
    }
    __syncthreads();
    if (warp == 0) {
        float v = (lane < SS) ? sc[lane] : -1e30f;
        float mx = v;
        #pragma unroll
        for (int o = 16; o > 0; o >>= 1) mx = fmaxf(mx, __shfl_xor_sync(0xFFFFFFFFu, mx, o));
        float e = (lane < SS) ? __expf(v - mx) : 0.0f;
        float ssum = e;
        #pragma unroll
        for (int o = 16; o > 0; o >>= 1) ssum += __shfl_xor_sync(0xFFFFFFFFu, ssum, o);
        if (lane < SS) a_sm[lane] = e / ssum;
    }
    __syncthreads();
    #pragma unroll
    for (int it = 0; it < 2; it++) {
        int d = tid + it * 256;
        const float* eb = encBse + (size_t)b * SS * 512 + d;
        float acc = 0.0f;
        #pragma unroll
        for (int s = 0; s < SS; s++) acc += a_sm[s] * eb[s * 512];
        bf16 hh, hl; split1(acc, hh, hl);
        catHi[(size_t)b * G3 + 256 + d] = hh;
        catLo[(size_t)b * G3 + 256 + d] = hl;
    }
}

// ---------------- host side ----------------
static inline float* symf(const void* s) {
    void* p = nullptr;
    cudaGetSymbolAddress(&p, s);
    return (float*)p;
}
static inline bf16* symb(const void* s) {
    void* p = nullptr;
    cudaGetSymbolAddress(&p, s);
    return (bf16*)p;
}

static void pgemm_s(cudaStream_t st,
                    const bf16* AH0, const bf16* AL0, const bf16* AH1, const bf16* AL1, int lda,
                    const bf16* BH0, const bf16* BL0, const bf16* BH1, const bf16* BL1, int ldb,
                    float* C0, float* C1, int ldc, int M, int N, int K,
                    const float* b0, const float* b1,
                    const float* gtab, const int* gidx, int gld, int z) {
    dim3 grid(N / 64, M / 128, z);
    tc_gemm_pair<<<grid, 256, PAIR_SMEM, st>>>(AH0, AL0, AH1, AL1, lda,
                                               BH0, BL0, BH1, BL1, ldb,
                                               C0, C1, ldc, K, b0, b1, gtab, gidx, gld);
}

extern "C" void kernel_launch(void* const* d_in, const int* in_sizes, int n_in,
                              void* d_out, int out_size) {
    const int*   src       = (const int*)  d_in[0];
    const int*   trg       = (const int*)  d_in[1];
    const float* enc_emb   = (const float*)d_in[2];
    const float* enc_Wih_f = (const float*)d_in[3];
    const float* enc_Whh_f = (const float*)d_in[4];
    const float* enc_bih_f = (const float*)d_in[5];
    const float* enc_bhh_f = (const float*)d_in[6];
    const float* enc_Wih_b = (const float*)d_in[7];
    const float* enc_Whh_b = (const float*)d_in[8];
    const float* enc_bih_b = (const float*)d_in[9];
    const float* enc_bhh_b = (const float*)d_in[10];
    const float* enc_fcW   = (const float*)d_in[11];
    const float* enc_fcb   = (const float*)d_in[12];
    const float* attn_Wh   = (const float*)d_in[13];
    const float* attn_We   = (const float*)d_in[14];
    const float* attn_b    = (const float*)d_in[15];
    const float* attn_v    = (const float*)d_in[16];
    const float* dec_emb   = (const float*)d_in[17];
    const float* dec_Wih   = (const float*)d_in[18];
    const float* dec_Whh   = (const float*)d_in[19];
    const float* dec_bih   = (const float*)d_in[20];
    const float* dec_bhh   = (const float*)d_in[21];
    const float* fcW       = (const float*)d_in[22];
    const float* fcb       = (const float*)d_in[23];
    float* out = (float*)d_out;

    cudaFuncSetAttribute(tc_gemm_pair,
                         cudaFuncAttributeMaxDynamicSharedMemorySize, PAIR_SMEM);
    cudaFuncSetAttribute(tc_gemm_f32,
                         cudaFuncAttributeMaxDynamicSharedMemorySize, F32_SMEM);

    float* encInF   = symf(g_encInF);
    float* encInB   = symf(g_encInB);
    float* decEmbW  = symf(g_decEmbW);
    float* decEmbFc = symf(g_decEmbFc);
    float* hFa = symf(g_hFa); float* hFb = symf(g_hFb);
    float* hBa = symf(g_hBa); float* hBb = symf(g_hBb);
    float* gh1 = symf(g_gh1); float* gh2 = symf(g_gh2);
    float* encBse  = symf(g_encBse);
    float* encProj = symf(g_encProj);
    float* hcat    = symf(g_hcat);
    float* dhA = symf(g_dhA); float* dhB = symf(g_dhB);
    float* hWhGh = symf(g_hWhGh);
    float* bcomb = symf(g_bcomb);

    bf16* hFaHi = symb(g_hFaHi); bf16* hFaLo = symb(g_hFaLo);
    bf16* hFbHi = symb(g_hFbHi); bf16* hFbLo = symb(g_hFbLo);
    bf16* hBaHi = symb(g_hBaHi); bf16* hBaLo = symb(g_hBaLo);
    bf16* hBbHi = symb(g_hBbHi); bf16* hBbLo = symb(g_hBbLo);
    bf16* dhAHi = symb(g_dhAHi); bf16* dhALo = symb(g_dhALo);
    bf16* dhBHi = symb(g_dhBHi); bf16* dhBLo = symb(g_dhBLo);
    bf16* WfHi = symb(g_WfHi); bf16* WfLo = symb(g_WfLo);
    bf16* WbHi = symb(g_WbHi); bf16* WbLo = symb(g_WbLo);
    bf16* WcombHi = symb(g_WcombHi); bf16* WcombLo = symb(g_WcombLo);
    bf16* Wih2Hi = symb(g_Wih2Hi); bf16* Wih2Lo = symb(g_Wih2Lo);
    bf16* fcW1Hi = symb(g_fcW1Hi); bf16* fcW1Lo = symb(g_fcW1Lo);
    bf16* catHi = symb(g_catHi); bf16* catLo = symb(g_catLo);

    // ---- side stream + events (host handles only; intentionally not destroyed —
    // kernel_launch is called only a handful of times, so leakage is bounded) ----
    cudaStream_t s2;
    cudaStreamCreateWithFlags(&s2, cudaStreamNonBlocking);
    cudaEvent_t evFork, evProjAll, evLogAll, evEnc[12], evG[TT - 1];
    cudaEventCreateWithFlags(&evFork, cudaEventDisableTiming);
    cudaEventCreateWithFlags(&evProjAll, cudaEventDisableTiming);
    cudaEventCreateWithFlags(&evLogAll, cudaEventDisableTiming);
    for (int i = 0; i < 12; i++) cudaEventCreateWithFlags(&evEnc[i], cudaEventDisableTiming);
    for (int i = 0; i < TT - 1; i++) cudaEventCreateWithFlags(&evG[i], cudaEventDisableTiming);

    // fork s2 from the (captured) main stream
    cudaEventRecord(evFork, 0);
    cudaStreamWaitEvent(s2, evFork, 0);

    // ---- prologue: main stream ----
    zero_kernel<<<(BB * HH + 255) / 256, 256>>>(hFa, BB * HH);
    zero_kernel<<<(BB * HH + 255) / 256, 256>>>(hBa, BB * HH);
    zero_kernel<<<(BB * HH / 2 + 255) / 256, 256>>>((float*)hFaHi, BB * HH / 2);
    zero_kernel<<<(BB * HH / 2 + 255) / 256, 256>>>((float*)hFaLo, BB * HH / 2);
    zero_kernel<<<(BB * HH / 2 + 255) / 256, 256>>>((float*)hBaHi, BB * HH / 2);
    zero_kernel<<<(BB * HH / 2 + 255) / 256, 256>>>((float*)hBaLo, BB * HH / 2);
    zero_kernel<<<(BB * VOUT + 255) / 256, 256>>>(out, BB * VOUT);
    {
        int total = VIN * G3 * 2 + VOUT * G3 + VOUT * VOUT;
        tables_kernel<<<(total + 255) / 256, 256>>>(
            enc_emb, dec_emb,
            enc_Wih_f, enc_bih_f, enc_Wih_b, enc_bih_b,
            dec_Wih, dec_bih, fcW + 768 * VOUT, fcb,
            encInF, encInB, decEmbW, decEmbFc);
    }
    wsplit_kernel<<<(HH * G3 + 255) / 256, 256>>>(enc_Whh_f, HH, G3, WfHi, WfLo);
    wsplit_kernel<<<(HH * G3 + 255) / 256, 256>>>(enc_Whh_b, HH, G3, WbHi, WbLo);

    // ---- prologue: side stream (decoder-only weights) ----
    comb_split_kernel<<<(HH * 1024 + 255) / 256, 256, 0, s2>>>(attn_Wh, dec_Whh, dec_bhh,
                                                               WcombHi, WcombLo, bcomb);
    wsplit_kernel<<<(512 * G3 + 255) / 256, 256, 0, s2>>>(dec_Wih + EE * G3, 512, G3,
                                                          Wih2Hi, Wih2Lo);
    wsplit_kernel<<<(G3 * VOUT + 255) / 256, 256, 0, s2>>>(fcW, G3, VOUT, fcW1Hi, fcW1Lo);

    // ---------------- encoder (main stream), per-slot encProj on side stream ----------------
    float* hf_in = hFa; float* hf_out = hFb;
    float* hb_in = hBa; float* hb_out = hBb;
    bf16 *hfiH = hFaHi, *hfiL = hFaLo, *hfoH = hFbHi, *hfoL = hFbLo;
    bf16 *hbiH = hBaHi, *hbiL = hBaLo, *hboH = hBbHi, *hboL = hBbLo;
    for (int s = 0; s < SS; s++) {
        pgemm_s(0, hfiH, hfiL, hbiH, hbiL, HH,
                WfHi, WfLo, WbHi, WbLo, HH,
                gh1, gh2, G3, BB, G3, HH,
                enc_bhh_f, enc_bhh_b, nullptr, nullptr, 0, 2);
        enc_gate_kernel<<<2 * BB, 256>>>(encInF, encInB, src, s,
                                         gh1, gh2, hf_in, hb_in, hf_out, hb_out,
                                         hfoH, hfoL, hboH, hboL, encBse);
        if (s >= 12) {
            // slots s and (SS-1-s) are now complete -> proj them on s2
            cudaEventRecord(evEnc[s - 12], 0);
            cudaStreamWaitEvent(s2, evEnc[s - 12], 0);
            int slots[2] = {s, SS - 1 - s};
            for (int q = 0; q < 2; q++) {
                int sl = slots[q];
                dim3 grid(HH / 64, BB / 128);
                tc_gemm_f32<<<grid, 256, F32_SMEM, s2>>>(
                    encBse + sl * 512, SS * 512, attn_We, HH,
                    encProj + sl * 256, SS * 256, 512, attn_b, 0);
            }
        }
        { float* t0 = hf_in; hf_in = hf_out; hf_out = t0; }
        { float* t1 = hb_in; hb_in = hb_out; hb_out = t1; }
        { bf16* t; t = hfiH; hfiH = hfoH; hfoH = t; t = hfiL; hfiL = hfoL; hfoL = t; }
        { bf16* t; t = hbiH; hbiH = hboH; hboH = t; t = hbiL; hbiL = hboL; hboL = t; }
    }
    // hidden = tanh([hf, hb] @ enc_fcW + enc_fcb) -> dhA (+pairs)   (main stream)
    concat2_kernel<<<(BB * 512 + 255) / 256, 256>>>(hf_in, HH, hb_in, HH, hcat, BB);
    {
        dim3 grid(HH / 64, BB / 128);
        tc_gemm_f32<<<grid, 256, F32_SMEM>>>(hcat, 512, enc_fcW, HH, dhA, HH,
                                             512, enc_fcb, 1);
    }
    split_kernel<<<(BB * HH + 255) / 256, 256>>>(dhA, dhAHi, dhALo, BB * HH);

    // all proj slots must be done before first attention
    cudaEventRecord(evProjAll, s2);
    cudaStreamWaitEvent(0, evProjAll, 0);

    // ---------------- decoder (main stream), per-step logits on side stream ----------------
    float* h_in = dhA; float* h_out = dhB;
    bf16 *hiH = dhAHi, *hiL = dhALo, *hoH = dhBHi, *hoL = dhBLo;
    for (int t = 0; t < TT - 1; t++) {
        bf16* slotHi = catHi + (size_t)t * BB * G3;
        bf16* slotLo = catLo + (size_t)t * BB * G3;
        // [hWh | gh] = h_in @ [attn_Wh | dec_Whh] + [0 | dec_bhh]
        pgemm_s(0, hiH, hiL, nullptr, nullptr, HH,
                WcombHi, WcombLo, nullptr, nullptr, HH,
                hWhGh, nullptr, 1024, BB, 1024, HH,
                bcomb, nullptr, nullptr, nullptr, 0, 1);
        // attention -> weighted pairs in slot cols [256:768)
        attn_kernel<<<BB, 256>>>(hWhGh, encProj, encBse, attn_v, slotHi, slotLo);
        // gi = weighted @ dec_Wih[300:812] + decEmbW[trg[t]]
        pgemm_s(0, slotHi + 256, slotLo + 256, nullptr, nullptr, G3,
                Wih2Hi, Wih2Lo, nullptr, nullptr, 512,
                gh1, nullptr, G3, BB, G3, 512,
                nullptr, nullptr, decEmbW, trg + t * BB, G3, 1);
        // gates -> h_out (fp32+pairs) and slot cols [0:256) pairs
        gru_gate_kernel<<<BB * HH / 256, 256>>>(gh1, G3, hWhGh + 256, 1024,
                                                h_in, h_out, hoH, hoL, slotHi, slotLo);
        // logits chunk for step t on side stream (overlaps next decoder step)
        cudaEventRecord(evG[t], 0);
        cudaStreamWaitEvent(s2, evG[t], 0);
        pgemm_s(s2, slotHi, slotLo, nullptr, nullptr, G3,
                fcW1Hi, fcW1Lo, nullptr, nullptr, G3,
                out + (size_t)(t + 1) * BB * VOUT, nullptr, VOUT, BB, VOUT, G3,
                nullptr, nullptr, decEmbFc, trg + t * BB, VOUT, 1);
        { float* t2 = h_in; h_in = h_out; h_out = t2; }
        { bf16* t3; t3 = hiH; hiH = hoH; hoH = t3; t3 = hiL; hiL = hoL; hoL = t3; }
    }

    // join side stream back into the captured main stream
    cudaEventRecord(evLogAll, s2);
    cudaStreamWaitEvent(0, evLogAll, 0);
}

// round 16
// speedup vs baseline: 1.1847x; 1.1847x over previous
#include <cuda_runtime.h>
#include <cuda_bf16.h>
#include <math.h>
#include <stdint.h>

// Problem constants
#define BB 2048
#define SS 24
#define TT 25
#define HH 256
#define EE 300
#define VIN 64
#define VOUT 128
#define G3 768   // 3*H

typedef __nv_bfloat16 bf16;

// ---------------- scratch (device globals; no allocation) ----------------
__device__ float g_encInF[VIN * G3];
__device__ float g_encInB[VIN * G3];
__device__ float g_decEmbW[VOUT * G3];
__device__ float g_decEmbFc[VOUT * VOUT];
__device__ float g_hFa[BB * HH];
__device__ float g_hFb[BB * HH];
__device__ float g_hBa[BB * HH];
__device__ float g_hBb[BB * HH];
__device__ float g_gh1[BB * G3];
__device__ float g_gh2[BB * G3];
__device__ float g_encBse[BB * SS * 2 * HH];   // (B, S, 512) fp32
__device__ float g_encProj[BB * SS * HH];      // (B, S, 256) fp32 (includes attn_b)
__device__ float g_hcat[BB * 2 * HH];
__device__ float g_dhA[BB * HH];
__device__ float g_dhB[BB * HH];
__device__ float g_hWhGh[BB * 1024];           // [hWh(256) | gh(768)] per row
__device__ float g_bcomb[1024];                // [0 | dec_bhh]

// bf16 pair planes (hi / lo), all k-contiguous
__device__ bf16 g_hFaHi[BB * HH]; __device__ bf16 g_hFaLo[BB * HH];
__device__ bf16 g_hFbHi[BB * HH]; __device__ bf16 g_hFbLo[BB * HH];
__device__ bf16 g_hBaHi[BB * HH]; __device__ bf16 g_hBaLo[BB * HH];
__device__ bf16 g_hBbHi[BB * HH]; __device__ bf16 g_hBbLo[BB * HH];
__device__ bf16 g_dhAHi[BB * HH]; __device__ bf16 g_dhALo[BB * HH];
__device__ bf16 g_dhBHi[BB * HH]; __device__ bf16 g_dhBLo[BB * HH];
__device__ bf16 g_WfHi[G3 * HH];  __device__ bf16 g_WfLo[G3 * HH];     // (768,256)
__device__ bf16 g_WbHi[G3 * HH];  __device__ bf16 g_WbLo[G3 * HH];     // (768,256)
__device__ bf16 g_WcombHi[1024 * HH]; __device__ bf16 g_WcombLo[1024 * HH]; // (1024,256)
__device__ bf16 g_Wih2Hi[G3 * 512];   __device__ bf16 g_Wih2Lo[G3 * 512];   // (768,512)
__device__ bf16 g_fcW1Hi[VOUT * G3];  __device__ bf16 g_fcW1Lo[VOUT * G3];  // (128,768)
__device__ bf16 g_WeHi[HH * 512];     __device__ bf16 g_WeLo[HH * 512];     // (256,512)
__device__ bf16 g_encBseHi[BB * SS * 512];
__device__ bf16 g_encBseLo[BB * SS * 512];
__device__ bf16 g_catHi[(TT - 1) * BB * G3];
__device__ bf16 g_catLo[(TT - 1) * BB * G3];

__device__ __forceinline__ void split1(float x, bf16& h, bf16& l) {
    h = __float2bfloat16(x);
    l = __float2bfloat16(x - __bfloat162float(h));
}

// ---------------- fused prologue kernel ----------------
// Segment sizes (elements)
#define SEG_Z1 (BB * HH)          // hFa
#define SEG_Z2 (BB * HH)          // hBa
#define SEG_ZP (4 * BB * HH / 2)  // 4 bf16 pair planes as u32
#define SEG_ZO (BB * VOUT)        // out slice 0
#define SEG_TF (VIN * G3)
#define SEG_TB (VIN * G3)
#define SEG_TD (VOUT * G3)
#define SEG_TC (VOUT * VOUT)
#define SEG_WF (HH * G3)
#define SEG_WB (HH * G3)
#define SEG_W2 (512 * G3)
#define SEG_W1 (G3 * VOUT)
#define SEG_WE (512 * HH)
#define SEG_CB (HH * 1024)
#define SEG_TOTAL (SEG_Z1 + SEG_Z2 + SEG_ZP + SEG_ZO + SEG_TF + SEG_TB + SEG_TD + \
                   SEG_TC + SEG_WF + SEG_WB + SEG_W2 + SEG_W1 + SEG_WE + SEG_CB)

__device__ __forceinline__ void table_elem(const float* __restrict__ emb,
                                           const float* __restrict__ W,
                                           const float* __restrict__ bias,
                                           float* __restrict__ out, int N, int idx) {
    int v = idx / N, n = idx % N;
    float acc = bias[n];
    const float* er = emb + (size_t)v * EE;
    #pragma unroll 4
    for (int e = 0; e < EE; e++) acc += er[e] * W[(size_t)e * N + n];
    out[(size_t)v * N + n] = acc;
}

__device__ __forceinline__ void wsplit_elem(const float* __restrict__ W, int K, int N,
                                            bf16* __restrict__ hi, bf16* __restrict__ lo,
                                            int t) {
    int k = t / N, n = t % N;
    bf16 h, l; split1(W[t], h, l);
    hi[(size_t)n * K + k] = h;
    lo[(size_t)n * K + k] = l;
}

__global__ void prologue_kernel(
    float* __restrict__ hFa, float* __restrict__ hBa,
    uint32_t* __restrict__ hFaHi, uint32_t* __restrict__ hFaLo,
    uint32_t* __restrict__ hBaHi, uint32_t* __restrict__ hBaLo,
    float* __restrict__ out0,
    const float* __restrict__ enc_emb, const float* __restrict__ dec_emb,
    const float* __restrict__ Wf, const float* __restrict__ bfb,
    const float* __restrict__ Wb, const float* __restrict__ bbb,
    const float* __restrict__ Wd, const float* __restrict__ bdb,
    const float* __restrict__ Wfc, const float* __restrict__ bfcb,
    float* __restrict__ encInF, float* __restrict__ encInB,
    float* __restrict__ decEmbW, float* __restrict__ decEmbFc,
    const float* __restrict__ enc_Whh_f, bf16* __restrict__ WfHi, bf16* __restrict__ WfLo,
    const float* __restrict__ enc_Whh_b, bf16* __restrict__ WbHi, bf16* __restrict__ WbLo,
    const float* __restrict__ Wih2src, bf16* __restrict__ W2Hi, bf16* __restrict__ W2Lo,
    const float* __restrict__ fcWsrc, bf16* __restrict__ W1Hi, bf16* __restrict__ W1Lo,
    const float* __restrict__ Wesrc, bf16* __restrict__ WeHi, bf16* __restrict__ WeLo,
    const float* __restrict__ attn_Wh, const float* __restrict__ dec_Whh,
    const float* __restrict__ dec_bhh,
    bf16* __restrict__ WcHi, bf16* __restrict__ WcLo, float* __restrict__ bcomb) {
    int t = blockIdx.x * blockDim.x + threadIdx.x;
    if (t < SEG_Z1) { hFa[t] = 0.0f; return; } t -= SEG_Z1;
    if (t < SEG_Z2) { hBa[t] = 0.0f; return; } t -= SEG_Z2;
    if (t < SEG_ZP) {
        const int q = BB * HH / 2;   // u32 elems per plane
        uint32_t* p = (t < q) ? hFaHi : (t < 2 * q) ? hFaLo : (t < 3 * q) ? hBaHi : hBaLo;
        p[t & (q - 1)] = 0u;
        return;
    } t -= SEG_ZP;
    if (t < SEG_ZO) { out0[t] = 0.0f; return; } t -= SEG_ZO;
    if (t < SEG_TF) { table_elem(enc_emb, Wf, bfb, encInF, G3, t); return; } t -= SEG_TF;
    if (t < SEG_TB) { table_elem(enc_emb, Wb, bbb, encInB, G3, t); return; } t -= SEG_TB;
    if (t < SEG_TD) { table_elem(dec_emb, Wd, bdb, decEmbW, G3, t); return; } t -= SEG_TD;
    if (t < SEG_TC) { table_elem(dec_emb, Wfc, bfcb, decEmbFc, VOUT, t); return; } t -= SEG_TC;
    if (t < SEG_WF) { wsplit_elem(enc_Whh_f, HH, G3, WfHi, WfLo, t); return; } t -= SEG_WF;
    if (t < SEG_WB) { wsplit_elem(enc_Whh_b, HH, G3, WbHi, WbLo, t); return; } t -= SEG_WB;
    if (t < SEG_W2) { wsplit_elem(Wih2src, 512, G3, W2Hi, W2Lo, t); return; } t -= SEG_W2;
    if (t < SEG_W1) { wsplit_elem(fcWsrc, G3, VOUT, W1Hi, W1Lo, t); return; } t -= SEG_W1;
    if (t < SEG_WE) { wsplit_elem(Wesrc, 512, HH, WeHi, WeLo, t); return; } t -= SEG_WE;
    if (t < SEG_CB) {
        int k = t >> 10, c = t & 1023;
        float v = (c < HH) ? attn_Wh[k * HH + c] : dec_Whh[k * G3 + (c - HH)];
        bf16 h, l; split1(v, h, l);
        WcHi[(size_t)c * HH + k] = h;
        WcLo[(size_t)c * HH + k] = l;
        if (k == 0) bcomb[c] = (c < HH) ? 0.0f : dec_bhh[c - HH];
        return;
    }
}

__global__ void concat2_kernel(const float* __restrict__ a, int na,
                               const float* __restrict__ b2, int nb,
                               float* __restrict__ dst, int rows) {
    int w = na + nb;
    int t = blockIdx.x * blockDim.x + threadIdx.x;
    if (t >= rows * w) return;
    int r = t / w, c = t % w;
    dst[t] = (c < na) ? a[r * na + c] : b2[r * nb + (c - na)];
}

// ==================== shared mma helpers ====================
#define SWZ(o) ((o) ^ (((o) >> 3) & 0x70))

__device__ __forceinline__ uint32_t smem_to_u32(const void* smem_ptr) {
    uint32_t addr;
    asm("{ .reg .u64 tmp; cvta.to.shared.u64 tmp, %1; cvt.u32.u64 %0, tmp; }"
        : "=r"(addr) : "l"(smem_ptr));
    return addr;
}

__device__ __forceinline__ void ldsm_x4(uint32_t* r, uint32_t addr) {
    asm volatile("ldmatrix.sync.aligned.m8n8.x4.shared.b16 {%0,%1,%2,%3}, [%4];"
        : "=r"(r[0]), "=r"(r[1]), "=r"(r[2]), "=r"(r[3]) : "r"(addr));
}

__device__ __forceinline__ void mma_bf16(float* c, const uint32_t* a,
                                         uint32_t b0, uint32_t b1) {
    asm volatile(
        "mma.sync.aligned.m16n8k16.row.col.f32.bf16.bf16.f32 "
        "{%0,%1,%2,%3}, {%4,%5,%6,%7}, {%8,%9}, {%0,%1,%2,%3};"
        : "+f"(c[0]), "+f"(c[1]), "+f"(c[2]), "+f"(c[3])
        : "r"(a[0]), "r"(a[1]), "r"(a[2]), "r"(a[3]), "r"(b0), "r"(b1));
}

__device__ __forceinline__ void split2(float x, float y, uint32_t& hi, uint32_t& lo) {
    bf16 hx = __float2bfloat16(x), hy = __float2bfloat16(y);
    float lxf = x - __bfloat162float(hx);
    float lyf = y - __bfloat162float(hy);
    bf16 lx = __float2bfloat16(lxf), ly = __float2bfloat16(lyf);
    hi = (uint32_t)__bfloat16_as_ushort(hx) | ((uint32_t)__bfloat16_as_ushort(hy) << 16);
    lo = (uint32_t)__bfloat16_as_ushort(lx) | ((uint32_t)__bfloat16_as_ushort(ly) << 16);
}

__device__ __forceinline__ void cpasync16(uint32_t s, const void* g) {
    asm volatile("cp.async.cg.shared.global [%0], [%1], 16;" :: "r"(s), "l"(g));
}
#define CP_COMMIT() asm volatile("cp.async.commit_group;" ::: "memory")
#define CP_WAIT0()  asm volatile("cp.async.wait_group 0;" ::: "memory")

// ==================== pair-operand tensor-core GEMM ====================
#define OFF_AHI  0
#define OFF_ALO  16384
#define OFF_BHI  32768
#define OFF_BLO  40960
#define PSTG     49152
#define PAIR_SMEM (2 * PSTG)

#define STAGE_CHUNK(kcv, stv) do {                                             \
    uint32_t _sbase = sb + (uint32_t)(stv) * PSTG;                             \
    _Pragma("unroll")                                                          \
    for (int _it = 0; _it < 4; _it++) {                                        \
        int _q = tid + _it * 256; int _r = _q >> 3, _j = _q & 7;               \
        size_t _go = (size_t)(row0 + _r) * lda + (kcv) + _j * 8;               \
        uint32_t _so = SWZ((uint32_t)(_r * 128 + _j * 16));                    \
        cpasync16(_sbase + OFF_AHI + _so, AH + _go);                           \
        cpasync16(_sbase + OFF_ALO + _so, AL + _go);                           \
    }                                                                          \
    _Pragma("unroll")                                                          \
    for (int _it = 0; _it < 2; _it++) {                                        \
        int _q = tid + _it * 256; int _r = _q >> 3, _j = _q & 7;               \
        size_t _go = (size_t)(col0 + _r) * ldb + (kcv) + _j * 8;               \
        uint32_t _so = SWZ((uint32_t)(_r * 128 + _j * 16));                    \
        cpasync16(_sbase + OFF_BHI + _so, BH + _go);                           \
        cpasync16(_sbase + OFF_BLO + _so, BL + _go);                           \
    }                                                                          \
    CP_COMMIT();                                                               \
} while (0)

__global__ __launch_bounds__(256) void tc_gemm_pair(
    const bf16* __restrict__ AH0, const bf16* __restrict__ AL0,
    const bf16* __restrict__ AH1, const bf16* __restrict__ AL1, int lda,
    const bf16* __restrict__ BH0, const bf16* __restrict__ BL0,
    const bf16* __restrict__ BH1, const bf16* __restrict__ BL1, int ldb,
    float* __restrict__ C0, float* __restrict__ C1, int ldc, int K,
    const float* __restrict__ bias0, const float* __restrict__ bias1,
    const float* __restrict__ gtab, const int* __restrict__ gidx, int gld) {
    extern __shared__ char smem[];
    uint32_t sb = smem_to_u32(smem);
    const bf16* AH = blockIdx.z ? AH1 : AH0;
    const bf16* AL = blockIdx.z ? AL1 : AL0;
    const bf16* BH = blockIdx.z ? BH1 : BH0;
    const bf16* BL = blockIdx.z ? BL1 : BL0;
    float* C = blockIdx.z ? C1 : C0;
    const float* bias = blockIdx.z ? bias1 : bias0;

    int tid = threadIdx.x;
    int wid = tid >> 5, lane = tid & 31;
    int wr = wid >> 1, wc = wid & 1;
    int row0 = blockIdx.y * 128, col0 = blockIdx.x * 64;

    float acc[2][4][4] = {};

    int a_r  = wr * 32 + (lane & 15);
    int a_kp = (lane >> 4) * 16;
    int b_n  = wc * 32 + ((lane >> 4) << 3) + (lane & 7);
    int b_kp = ((lane >> 3) & 1) * 16;

    int nc = K >> 6;
    STAGE_CHUNK(0, 0);
    CP_WAIT0();
    __syncthreads();

    for (int c = 0; c < nc; c++) {
        int cur = c & 1;
        if (c + 1 < nc) STAGE_CHUNK((c + 1) << 6, cur ^ 1);

        uint32_t sb2 = sb + (uint32_t)cur * PSTG;
        #pragma unroll
        for (int ks = 0; ks < 4; ks++) {
            uint32_t ah[2][4], al[2][4];
            #pragma unroll
            for (int rt = 0; rt < 2; rt++) {
                int r = a_r + rt * 16;
                uint32_t off = (uint32_t)(r * 128) +
                               (uint32_t)((ks * 32 + a_kp) ^ ((r & 7) << 4));
                ldsm_x4(ah[rt], sb2 + OFF_AHI + off);
                ldsm_x4(al[rt], sb2 + OFF_ALO + off);
            }
            uint32_t bh[2][4], bl[2][4];
            #pragma unroll
            for (int cp = 0; cp < 2; cp++) {
                int n = b_n + cp * 16;
                uint32_t off = (uint32_t)(n * 128) +
                               (uint32_t)((ks * 32 + b_kp) ^ ((n & 7) << 4));
                ldsm_x4(bh[cp], sb2 + OFF_BHI + off);
                ldsm_x4(bl[cp], sb2 + OFF_BLO + off);
            }
            #pragma unroll
            for (int rt = 0; rt < 2; rt++)
                #pragma unroll
                for (int ct = 0; ct < 4; ct++) {
                    int cp = ct >> 1, o = (ct & 1) * 2;
                    mma_bf16(acc[rt][ct], ah[rt], bh[cp][o], bh[cp][o + 1]);
                    mma_bf16(acc[rt][ct], ah[rt], bl[cp][o], bl[cp][o + 1]);
                    mma_bf16(acc[rt][ct], al[rt], bh[cp][o], bh[cp][o + 1]);
                }
        }
        if (c + 1 < nc) CP_WAIT0();
        __syncthreads();
    }

    // epilogue
    #pragma unroll
    for (int rt = 0; rt < 2; rt++) {
        int m0 = row0 + wr * 32 + rt * 16 + (lane >> 2);
        int m1 = m0 + 8;
        const float* g0 = gtab ? (gtab + (size_t)gidx[m0] * gld) : nullptr;
        const float* g1 = gtab ? (gtab + (size_t)gidx[m1] * gld) : nullptr;
        #pragma unroll
        for (int ct = 0; ct < 4; ct++) {
            int n = col0 + wc * 32 + ct * 8 + (lane & 3) * 2;
            float v0 = acc[rt][ct][0], v1 = acc[rt][ct][1];
            float v2 = acc[rt][ct][2], v3 = acc[rt][ct][3];
            if (bias) { float b0 = bias[n], b1 = bias[n + 1]; v0 += b0; v1 += b1; v2 += b0; v3 += b1; }
            if (g0) { v0 += g0[n]; v1 += g0[n + 1]; }
            if (g1) { v2 += g1[n]; v3 += g1[n + 1]; }
            *reinterpret_cast<float2*>(&C[(size_t)m0 * ldc + n]) = make_float2(v0, v1);
            *reinterpret_cast<float2*>(&C[(size_t)m1 * ldc + n]) = make_float2(v2, v3);
        }
    }
}

// ==================== fp32-operand tensor-core GEMM (enc_fc only) ====================
#define F32_SMEM 49152

__global__ __launch_bounds__(256) void tc_gemm_f32(
    const float* __restrict__ A, int lda,
    const float* __restrict__ Bm, int ldb,
    float* __restrict__ C, bf16* __restrict__ Chi, bf16* __restrict__ Clo, int ldc,
    int K, const float* __restrict__ bias, int act) {
    extern __shared__ char smem[];
    uint32_t sb = smem_to_u32(smem);

    int tid = threadIdx.x;
    int wid = tid >> 5, lane = tid & 31;
    int wr = wid >> 1, wc = wid & 1;
    int row0 = blockIdx.y * 128, col0 = blockIdx.x * 64;

    float acc[2][4][4] = {};

    int a_r  = wr * 32 + (lane & 15);
    int a_kp = (lane >> 4) * 16;
    int b_n  = wc * 32 + ((lane >> 4) << 3) + (lane & 7);
    int b_kp = ((lane >> 3) & 1) * 16;

    for (int kc = 0; kc < K; kc += 64) {
        #pragma unroll
        for (int it = 0; it < 8; it++) {
            int q = tid + it * 256;
            int r = q >> 4;
            int k4 = (q & 15) * 4;
            float4 v = *reinterpret_cast<const float4*>(
                &A[(size_t)(row0 + r) * lda + kc + k4]);
            uint32_t h01, l01, h23, l23;
            split2(v.x, v.y, h01, l01);
            split2(v.z, v.w, h23, l23);
            uint32_t off = SWZ((uint32_t)(r * 128 + k4 * 2));
            *reinterpret_cast<uint2*>(smem + OFF_AHI + off) = make_uint2(h01, h23);
            *reinterpret_cast<uint2*>(smem + OFF_ALO + off) = make_uint2(l01, l23);
        }
        {
            int n = tid & 63;
            int kh = tid >> 6;
            #pragma unroll
            for (int i = 0; i < 8; i++) {
                int k = kh * 16 + i * 2;
                float b0f = Bm[(size_t)(kc + k) * ldb + col0 + n];
                float b1f = Bm[(size_t)(kc + k + 1) * ldb + col0 + n];
                uint32_t h, l;
                split2(b0f, b1f, h, l);
                uint32_t off = SWZ((uint32_t)(n * 128 + k * 2));
                *reinterpret_cast<uint32_t*>(smem + OFF_BHI + off) = h;
                *reinterpret_cast<uint32_t*>(smem + OFF_BLO + off) = l;
            }
        }
        __syncthreads();

        #pragma unroll
        for (int ks = 0; ks < 4; ks++) {
            uint32_t ah[2][4], al[2][4];
            #pragma unroll
            for (int rt = 0; rt < 2; rt++) {
                int r = a_r + rt * 16;
                uint32_t off = (uint32_t)(r * 128) +
                               (uint32_t)((ks * 32 + a_kp) ^ ((r & 7) << 4));
                ldsm_x4(ah[rt], sb + OFF_AHI + off);
                ldsm_x4(al[rt], sb + OFF_ALO + off);
            }
            uint32_t bh[2][4], bl[2][4];
            #pragma unroll
            for (int cp = 0; cp < 2; cp++) {
                int n = b_n + cp * 16;
                uint32_t off = (uint32_t)(n * 128) +
                               (uint32_t)((ks * 32 + b_kp) ^ ((n & 7) << 4));
                ldsm_x4(bh[cp], sb + OFF_BHI + off);
                ldsm_x4(bl[cp], sb + OFF_BLO + off);
            }
            #pragma unroll
            for (int rt = 0; rt < 2; rt++)
                #pragma unroll
                for (int ct = 0; ct < 4; ct++) {
                    int cp = ct >> 1, o = (ct & 1) * 2;
                    mma_bf16(acc[rt][ct], ah[rt], bh[cp][o], bh[cp][o + 1]);
                    mma_bf16(acc[rt][ct], ah[rt], bl[cp][o], bl[cp][o + 1]);
                    mma_bf16(acc[rt][ct], al[rt], bh[cp][o], bh[cp][o + 1]);
                }
        }
        __syncthreads();
    }

    #pragma unroll
    for (int rt = 0; rt < 2; rt++) {
        int m0 = row0 + wr * 32 + rt * 16 + (lane >> 2);
        int m1 = m0 + 8;
        #pragma unroll
        for (int ct = 0; ct < 4; ct++) {
            int n = col0 + wc * 32 + ct * 8 + (lane & 3) * 2;
            float v0 = acc[rt][ct][0], v1 = acc[rt][ct][1];
            float v2 = acc[rt][ct][2], v3 = acc[rt][ct][3];
            if (bias) { float b0 = bias[n], b1 = bias[n + 1]; v0 += b0; v1 += b1; v2 += b0; v3 += b1; }
            if (act) { v0 = tanhf(v0); v1 = tanhf(v1); v2 = tanhf(v2); v3 = tanhf(v3); }
            *reinterpret_cast<float2*>(&C[(size_t)m0 * ldc + n]) = make_float2(v0, v1);
            *reinterpret_cast<float2*>(&C[(size_t)m1 * ldc + n]) = make_float2(v2, v3);
            if (Chi) {
                bf16 h, l;
                split1(v0, h, l); Chi[(size_t)m0 * ldc + n] = h;     Clo[(size_t)m0 * ldc + n] = l;
                split1(v1, h, l); Chi[(size_t)m0 * ldc + n + 1] = h; Clo[(size_t)m0 * ldc + n + 1] = l;
                split1(v2, h, l); Chi[(size_t)m1 * ldc + n] = h;     Clo[(size_t)m1 * ldc + n] = l;
                split1(v3, h, l); Chi[(size_t)m1 * ldc + n + 1] = h; Clo[(size_t)m1 * ldc + n + 1] = l;
            }
        }
    }
}

// ---------------- GRU gate kernels ----------------
__global__ void gru_gate_kernel(const float* __restrict__ gi, int gild,
                                const float* __restrict__ gh, int ghld,
                                const float* __restrict__ hprev,
                                float* __restrict__ hout,
                                bf16* __restrict__ houtHi, bf16* __restrict__ houtLo,
                                bf16* __restrict__ catHi, bf16* __restrict__ catLo) {
    int t = blockIdx.x * blockDim.x + threadIdx.x;
    int b = t >> 8;
    int j = t & 255;
    const float* g = gi + (size_t)b * gild;
    const float* G = gh + (size_t)b * ghld;
    float r = 1.0f / (1.0f + __expf(-(g[j] + G[j])));
    float z = 1.0f / (1.0f + __expf(-(g[j + HH] + G[j + HH])));
    float n = tanhf(g[j + 2 * HH] + r * G[j + 2 * HH]);
    float hp = hprev[b * HH + j];
    float hv = (1.0f - z) * n + z * hp;
    hout[b * HH + j] = hv;
    bf16 hh, hl; split1(hv, hh, hl);
    houtHi[b * HH + j] = hh;
    houtLo[b * HH + j] = hl;
    catHi[(size_t)b * G3 + j] = hh;
    catLo[(size_t)b * G3 + j] = hl;
}

__global__ void enc_gate_kernel(const float* __restrict__ giTabF,
                                const float* __restrict__ giTabB,
                                const int* __restrict__ src, int s,
                                const float* __restrict__ ghF,
                                const float* __restrict__ ghB,
                                const float* __restrict__ hprevF,
                                const float* __restrict__ hprevB,
                                float* __restrict__ houtF,
                                float* __restrict__ houtB,
                                bf16* __restrict__ houtFHi, bf16* __restrict__ houtFLo,
                                bf16* __restrict__ houtBHi, bf16* __restrict__ houtBLo,
                                float* __restrict__ encBse,
                                bf16* __restrict__ encBseHi, bf16* __restrict__ encBseLo) {
    int dir = blockIdx.x >> 11;
    int b = blockIdx.x & (BB - 1);
    int j = threadIdx.x;
    int step = dir ? (SS - 1 - s) : s;
    int tok = src[step * BB + b];
    const float* g = (dir ? giTabB : giTabF) + (size_t)tok * G3;
    const float* G = (dir ? ghB : ghF) + (size_t)b * G3;
    float r = 1.0f / (1.0f + __expf(-(g[j] + G[j])));
    float z = 1.0f / (1.0f + __expf(-(g[j + HH] + G[j + HH])));
    float n = tanhf(g[j + 2 * HH] + r * G[j + 2 * HH]);
    const float* hp = (dir ? hprevB : hprevF) + b * HH;
    float hv = (1.0f - z) * n + z * hp[j];
    (dir ? houtB : houtF)[b * HH + j] = hv;
    bf16 hh, hl; split1(hv, hh, hl);
    (dir ? houtBHi : houtFHi)[b * HH + j] = hh;
    (dir ? houtBLo : houtFLo)[b * HH + j] = hl;
    size_t eidx = ((size_t)b * SS + step) * 512 + dir * 256 + j;
    encBse[eidx] = hv;
    encBseHi[eidx] = hh;
    encBseLo[eidx] = hl;
}

// ---------------- fused attention kernel (proj already contains attn_b) ----------------
__global__ __launch_bounds__(256) void attn_kernel(
    const float* __restrict__ hWhGh,   // B x 1024 (first 256 = hWh)
    const float* __restrict__ proj,    // B x S x 256 (with attn_b folded in)
    const float* __restrict__ encBse,  // B x S x 512
    const float* __restrict__ attn_v,  // 256
    bf16* __restrict__ catHi, bf16* __restrict__ catLo) {  // slot base
    int b = blockIdx.x;
    int tid = threadIdx.x;
    __shared__ float hb[256];
    __shared__ float vsh[256];
    __shared__ float sc[SS];
    __shared__ float a_sm[SS];
    hb[tid] = hWhGh[b * 1024 + tid];
    vsh[tid] = attn_v[tid];
    __syncthreads();
    int warp = tid >> 5, lane = tid & 31;
    for (int s = warp; s < SS; s += 8) {
        const float* pr = proj + ((size_t)b * SS + s) * 256;
        float sum = 0.0f;
        #pragma unroll
        for (int i = 0; i < 8; i++) {
            int k = lane + i * 32;
            sum += tanhf(hb[k] + pr[k]) * vsh[k];
        }
        #pragma unroll
        for (int o = 16; o > 0; o >>= 1) sum += __shfl_xor_sync(0xFFFFFFFFu, sum, o);
        if (lane == 0) sc[s] = sum;
    }
    __syncthreads();
    if (warp == 0) {
        float v = (lane < SS) ? sc[lane] : -1e30f;
        float mx = v;
        #pragma unroll
        for (int o = 16; o > 0; o >>= 1) mx = fmaxf(mx, __shfl_xor_sync(0xFFFFFFFFu, mx, o));
        float e = (lane < SS) ? __expf(v - mx) : 0.0f;
        float ssum = e;
        #pragma unroll
        for (int o = 16; o > 0; o >>= 1) ssum += __shfl_xor_sync(0xFFFFFFFFu, ssum, o);
        if (lane < SS) a_sm[lane] = e / ssum;
    }
    __syncthreads();
    #pragma unroll
    for (int it = 0; it < 2; it++) {
        int d = tid + it * 256;
        const float* eb = encBse + (size_t)b * SS * 512 + d;
        float acc = 0.0f;
        #pragma unroll
        for (int s = 0; s < SS; s++) acc += a_sm[s] * eb[s * 512];
        bf16 hh, hl; split1(acc, hh, hl);
        catHi[(size_t)b * G3 + 256 + d] = hh;
        catLo[(size_t)b * G3 + 256 + d] = hl;
    }
}

// ---------------- host side ----------------
static inline float* symf(const void* s) {
    void* p = nullptr;
    cudaGetSymbolAddress(&p, s);
    return (float*)p;
}
static inline bf16* symb(const void* s) {
    void* p = nullptr;
    cudaGetSymbolAddress(&p, s);
    return (bf16*)p;
}

static void pgemm(const bf16* AH0, const bf16* AL0, const bf16* AH1, const bf16* AL1, int lda,
                  const bf16* BH0, const bf16* BL0, const bf16* BH1, const bf16* BL1, int ldb,
                  float* C0, float* C1, int ldc, int M, int N, int K,
                  const float* b0, const float* b1,
                  const float* gtab, const int* gidx, int gld, int z) {
    dim3 grid(N / 64, M / 128, z);
    tc_gemm_pair<<<grid, 256, PAIR_SMEM>>>(AH0, AL0, AH1, AL1, lda,
                                           BH0, BL0, BH1, BL1, ldb,
                                           C0, C1, ldc, K, b0, b1, gtab, gidx, gld);
}

extern "C" void kernel_launch(void* const* d_in, const int* in_sizes, int n_in,
                              void* d_out, int out_size) {
    const int*   src       = (const int*)  d_in[0];
    const int*   trg       = (const int*)  d_in[1];
    const float* enc_emb   = (const float*)d_in[2];
    const float* enc_Wih_f = (const float*)d_in[3];
    const float* enc_Whh_f = (const float*)d_in[4];
    const float* enc_bih_f = (const float*)d_in[5];
    const float* enc_bhh_f = (const float*)d_in[6];
    const float* enc_Wih_b = (const float*)d_in[7];
    const float* enc_Whh_b = (const float*)d_in[8];
    const float* enc_bih_b = (const float*)d_in[9];
    const float* enc_bhh_b = (const float*)d_in[10];
    const float* enc_fcW   = (const float*)d_in[11];
    const float* enc_fcb   = (const float*)d_in[12];
    const float* attn_Wh   = (const float*)d_in[13];
    const float* attn_We   = (const float*)d_in[14];
    const float* attn_b    = (const float*)d_in[15];
    const float* attn_v    = (const float*)d_in[16];
    const float* dec_emb   = (const float*)d_in[17];
    const float* dec_Wih   = (const float*)d_in[18];
    const float* dec_Whh   = (const float*)d_in[19];
    const float* dec_bih   = (const float*)d_in[20];
    const float* dec_bhh   = (const float*)d_in[21];
    const float* fcW       = (const float*)d_in[22];
    const float* fcb       = (const float*)d_in[23];
    float* out = (float*)d_out;

    cudaFuncSetAttribute(tc_gemm_pair,
                         cudaFuncAttributeMaxDynamicSharedMemorySize, PAIR_SMEM);
    cudaFuncSetAttribute(tc_gemm_f32,
                         cudaFuncAttributeMaxDynamicSharedMemorySize, F32_SMEM);

    float* encInF   = symf(g_encInF);
    float* encInB   = symf(g_encInB);
    float* decEmbW  = symf(g_decEmbW);
    float* decEmbFc = symf(g_decEmbFc);
    float* hFa = symf(g_hFa); float* hFb = symf(g_hFb);
    float* hBa = symf(g_hBa); float* hBb = symf(g_hBb);
    float* gh1 = symf(g_gh1); float* gh2 = symf(g_gh2);
    float* encBse  = symf(g_encBse);
    float* encProj = symf(g_encProj);
    float* hcat    = symf(g_hcat);
    float* dhA = symf(g_dhA); float* dhB = symf(g_dhB);
    float* hWhGh = symf(g_hWhGh);
    float* bcomb = symf(g_bcomb);

    bf16* hFaHi = symb(g_hFaHi); bf16* hFaLo = symb(g_hFaLo);
    bf16* hFbHi = symb(g_hFbHi); bf16* hFbLo = symb(g_hFbLo);
    bf16* hBaHi = symb(g_hBaHi); bf16* hBaLo = symb(g_hBaLo);
    bf16* hBbHi = symb(g_hBbHi); bf16* hBbLo = symb(g_hBbLo);
    bf16* dhAHi = symb(g_dhAHi); bf16* dhALo = symb(g_dhALo);
    bf16* dhBHi = symb(g_dhBHi); bf16* dhBLo = symb(g_dhBLo);
    bf16* WfHi = symb(g_WfHi); bf16* WfLo = symb(g_WfLo);
    bf16* WbHi = symb(g_WbHi); bf16* WbLo = symb(g_WbLo);
    bf16* WcombHi = symb(g_WcombHi); bf16* WcombLo = symb(g_WcombLo);
    bf16* Wih2Hi = symb(g_Wih2Hi); bf16* Wih2Lo = symb(g_Wih2Lo);
    bf16* fcW1Hi = symb(g_fcW1Hi); bf16* fcW1Lo = symb(g_fcW1Lo);
    bf16* WeHi = symb(g_WeHi); bf16* WeLo = symb(g_WeLo);
    bf16* encBseHi = symb(g_encBseHi); bf16* encBseLo = symb(g_encBseLo);
    bf16* catHi = symb(g_catHi); bf16* catLo = symb(g_catLo);

    // ---- single fused prologue launch (launch #0) ----
    prologue_kernel<<<(SEG_TOTAL + 255) / 256, 256>>>(
        hFa, hBa,
        (uint32_t*)hFaHi, (uint32_t*)hFaLo, (uint32_t*)hBaHi, (uint32_t*)hBaLo,
        out,
        enc_emb, dec_emb,
        enc_Wih_f, enc_bih_f, enc_Wih_b, enc_bih_b,
        dec_Wih, dec_bih, fcW + 768 * VOUT, fcb,
        encInF, encInB, decEmbW, decEmbFc,
        enc_Whh_f, WfHi, WfLo,
        enc_Whh_b, WbHi, WbLo,
        dec_Wih + EE * G3, Wih2Hi, Wih2Lo,
        fcW, fcW1Hi, fcW1Lo,
        attn_We, WeHi, WeLo,
        attn_Wh, dec_Whh, dec_bhh, WcombHi, WcombLo, bcomb);

    // ---------------- encoder: bidirectional GRU, both directions batched ----------------
    float* hf_in = hFa; float* hf_out = hFb;
    float* hb_in = hBa; float* hb_out = hBb;
    bf16 *hfiH = hFaHi, *hfiL = hFaLo, *hfoH = hFbHi, *hfoL = hFbLo;
    bf16 *hbiH = hBaHi, *hbiL = hBaLo, *hboH = hBbHi, *hboL = hBbLo;
    for (int s = 0; s < SS; s++) {
        pgemm(hfiH, hfiL, hbiH, hbiL, HH,
              WfHi, WfLo, WbHi, WbLo, HH,
              gh1, gh2, G3, BB, G3, HH,
              enc_bhh_f, enc_bhh_b, nullptr, nullptr, 0, 2);
        enc_gate_kernel<<<2 * BB, 256>>>(encInF, encInB, src, s,
                                         gh1, gh2, hf_in, hb_in, hf_out, hb_out,
                                         hfoH, hfoL, hboH, hboL,
                                         encBse, encBseHi, encBseLo);
        { float* t0 = hf_in; hf_in = hf_out; hf_out = t0; }
        { float* t1 = hb_in; hb_in = hb_out; hb_out = t1; }
        { bf16* t; t = hfiH; hfiH = hfoH; hfoH = t; t = hfiL; hfiL = hfoL; hfoL = t; }
        { bf16* t; t = hbiH; hbiH = hboH; hboH = t; t = hbiL; hbiL = hboL; hboL = t; }
    }
    // hidden = tanh([hf, hb] @ enc_fcW + enc_fcb) -> dhA (+pairs fused in epilogue)
    concat2_kernel<<<(BB * 512 + 255) / 256, 256>>>(hf_in, HH, hb_in, HH, hcat, BB);
    {
        dim3 grid(HH / 64, BB / 128);
        tc_gemm_f32<<<grid, 256, F32_SMEM>>>(hcat, 512, enc_fcW, HH,
                                             dhA, dhAHi, dhALo, HH,
                                             512, enc_fcb, 1);
    }

    // enc_proj = enc_bse @ attn_We + attn_b : pair-operand GEMM on encBse pairs
    pgemm(encBseHi, encBseLo, nullptr, nullptr, 512,
          WeHi, WeLo, nullptr, nullptr, 512,
          encProj, nullptr, HH, BB * SS, HH, 512,
          attn_b, nullptr, nullptr, nullptr, 0, 1);

    // ---------------- decoder ----------------
    float* h_in = dhA; float* h_out = dhB;
    bf16 *hiH = dhAHi, *hiL = dhALo, *hoH = dhBHi, *hoL = dhBLo;
    for (int t = 0; t < TT - 1; t++) {
        bf16* slotHi = catHi + (size_t)t * BB * G3;
        bf16* slotLo = catLo + (size_t)t * BB * G3;
        // [hWh | gh] = h_in @ [attn_Wh | dec_Whh] + [0 | dec_bhh]
        pgemm(hiH, hiL, nullptr, nullptr, HH,
              WcombHi, WcombLo, nullptr, nullptr, HH,
              hWhGh, nullptr, 1024, BB, 1024, HH,
              bcomb, nullptr, nullptr, nullptr, 0, 1);
        // attention -> weighted pairs in slot cols [256:768)
        attn_kernel<<<BB, 256>>>(hWhGh, encProj, encBse, attn_v, slotHi, slotLo);
        // gi = weighted @ dec_Wih[300:812] + decEmbW[trg[t]]
        pgemm(slotHi + 256, slotLo + 256, nullptr, nullptr, G3,
              Wih2Hi, Wih2Lo, nullptr, nullptr, 512,
              gh1, nullptr, G3, BB, G3, 512,
              nullptr, nullptr, decEmbW, trg + t * BB, G3, 1);
        // gates -> h_out (fp32+pairs) and slot cols [0:256) pairs
        gru_gate_kernel<<<BB * HH / 256, 256>>>(gh1, G3, hWhGh + 256, 1024,
                                                h_in, h_out, hoH, hoL, slotHi, slotLo);
        { float* t2 = h_in; h_in = h_out; h_out = t2; }
        { bf16* t3; t3 = hiH; hiH = hoH; hoH = t3; t3 = hiL; hiL = hoL; hoL = t3; }
    }

    // All logits at once: (24*2048, 768) @ fcW[0:768] + decEmbFc[trg[:-1]]
    pgemm(catHi, catLo, nullptr, nullptr, G3,
          fcW1Hi, fcW1Lo, nullptr, nullptr, G3,
          out + (size_t)BB * VOUT, nullptr, VOUT, (TT - 1) * BB, VOUT, G3,
          nullptr, nullptr, decEmbFc, trg, VOUT, 1);
}